// round 9
// baseline (speedup 1.0000x reference)
#include <cuda_runtime.h>

// Problem constants (fixed shapes from reference setup_inputs):
//   x, out_ae : (16, 3, 512, 512) fp32
//   out_seg   : (16, 1, 512, 512) fp32
//   out       : scalar fp32 loss
#define N_      16
#define C_      3
#define HW_     (512 * 512)          // 262144
#define NHW_    (N_ * HW_)           // 4194304  (pos+neg total over (n,1,h,w))
#define HW4_    (HW_ / 4)            // 65536    (float4 units per plane)
#define NHW4_   (NHW_ / 4)           // 1048576  (float4 work items)
#define NCHUNKS (NHW4_ / 64)         // 16384    (64-float4 chunks, one per warp-iter)
#define BF_THRESH 0.5f

#define BLOCK_THREADS 256
#define BLOCKS_PER_SM 3              // 85-reg budget: room for 14 live LDG.128 dests
#define GRID_BLOCKS   (148 * BLOCKS_PER_SM)   // 444: one resident wave
#define TOTAL_WARPS   (GRID_BLOCKS * (BLOCK_THREADS / 32))  // 3552

// Device-global accumulators. Zero-initialized at module load; the
// finalizing block resets them so every graph replay starts clean.
__device__ float        g_pos_sum = 0.0f;
__device__ float        g_tot_sum = 0.0f;
__device__ float        g_pos_cnt = 0.0f;
__device__ unsigned int g_done    = 0u;

__global__ __launch_bounds__(BLOCK_THREADS, BLOCKS_PER_SM)
void wmse_kernel(const float4* __restrict__ x4,
                 const float4* __restrict__ ae4,
                 const float4* __restrict__ seg4,
                 float* __restrict__ out)
{
    float pos_s = 0.0f;   // sum of diff^2 where seg > 0.5 (over all c)
    float tot_s = 0.0f;   // sum of diff^2 over everything
    float cnt   = 0.0f;   // count of seg > 0.5 (over n,h,w only)

    const int lane = threadIdx.x & 31;
    const int warp = blockIdx.x * (BLOCK_THREADS / 32) + (threadIdx.x >> 5);

    // Each warp-iteration covers one 64-float4 chunk: lane handles float4
    // indices chunk*64+lane and chunk*64+32+lane (both fully coalesced).
    // A chunk never crosses an n-plane boundary (HW4_ = 65536 is a multiple of 64).
    for (int chunk = warp; chunk < NCHUNKS; chunk += TOTAL_WARPS) {
        const int n    = chunk >> 10;                         // (chunk*64) >> 16
        const int hwq1 = ((chunk << 6) & 0xFFFF) + lane;      // within-plane float4 idx
        const int g1   = (chunk << 6) + lane;                 // seg float4 idx
        const int b1   = n * (C_ * HW4_) + hwq1;
        const int b2   = b1 + 32;

        // ---- issue ALL 14 independent loads first (front-batched MLP) ----
        const float4 s1  = seg4[g1];
        const float4 s2  = seg4[g1 + 32];
        const float4 xA0 = x4 [b1 + 0 * HW4_];
        const float4 aA0 = ae4[b1 + 0 * HW4_];
        const float4 xA1 = x4 [b1 + 1 * HW4_];
        const float4 aA1 = ae4[b1 + 1 * HW4_];
        const float4 xA2 = x4 [b1 + 2 * HW4_];
        const float4 aA2 = ae4[b1 + 2 * HW4_];
        const float4 xB0 = x4 [b2 + 0 * HW4_];
        const float4 aB0 = ae4[b2 + 0 * HW4_];
        const float4 xB1 = x4 [b2 + 1 * HW4_];
        const float4 aB1 = ae4[b2 + 1 * HW4_];
        const float4 xB2 = x4 [b2 + 2 * HW4_];
        const float4 aB2 = ae4[b2 + 2 * HW4_];

        // ---- then compute ----
        const float pAx = s1.x > BF_THRESH ? 1.0f : 0.0f;
        const float pAy = s1.y > BF_THRESH ? 1.0f : 0.0f;
        const float pAz = s1.z > BF_THRESH ? 1.0f : 0.0f;
        const float pAw = s1.w > BF_THRESH ? 1.0f : 0.0f;
        const float pBx = s2.x > BF_THRESH ? 1.0f : 0.0f;
        const float pBy = s2.y > BF_THRESH ? 1.0f : 0.0f;
        const float pBz = s2.z > BF_THRESH ? 1.0f : 0.0f;
        const float pBw = s2.w > BF_THRESH ? 1.0f : 0.0f;
        cnt += ((pAx + pAy) + (pAz + pAw)) + ((pBx + pBy) + (pBz + pBw));

        #define ACC(av, xv, px, py, pz, pw)                                   \
        {                                                                     \
            const float dx = (av).x - (xv).x, dy = (av).y - (xv).y;           \
            const float dz = (av).z - (xv).z, dw = (av).w - (xv).w;           \
            const float ex = dx * dx, ey = dy * dy;                           \
            const float ez = dz * dz, ew = dw * dw;                           \
            tot_s += (ex + ey) + (ez + ew);                                   \
            pos_s += (ex * (px) + ey * (py)) + (ez * (pz) + ew * (pw));       \
        }
        ACC(aA0, xA0, pAx, pAy, pAz, pAw)
        ACC(aA1, xA1, pAx, pAy, pAz, pAw)
        ACC(aA2, xA2, pAx, pAy, pAz, pAw)
        ACC(aB0, xB0, pBx, pBy, pBz, pBw)
        ACC(aB1, xB1, pBx, pBy, pBz, pBw)
        ACC(aB2, xB2, pBx, pBy, pBz, pBw)
        #undef ACC
    }

    // ---- intra-warp reduction ----
    #pragma unroll
    for (int o = 16; o > 0; o >>= 1) {
        pos_s += __shfl_down_sync(0xFFFFFFFFu, pos_s, o);
        tot_s += __shfl_down_sync(0xFFFFFFFFu, tot_s, o);
        cnt   += __shfl_down_sync(0xFFFFFFFFu, cnt,   o);
    }

    // ---- intra-block reduction (8 warps) ----
    __shared__ float sp[8], st[8], sc[8];
    const int wid = threadIdx.x >> 5;
    if (lane == 0) { sp[wid] = pos_s; st[wid] = tot_s; sc[wid] = cnt; }
    __syncthreads();

    if (threadIdx.x == 0) {
        float bp = 0.0f, bt = 0.0f, bc = 0.0f;
        #pragma unroll
        for (int i = 0; i < BLOCK_THREADS / 32; ++i) {
            bp += sp[i]; bt += st[i]; bc += sc[i];
        }

        atomicAdd(&g_pos_sum, bp);
        atomicAdd(&g_tot_sum, bt);
        atomicAdd(&g_pos_cnt, bc);
        __threadfence();

        const unsigned int ticket = atomicAdd(&g_done, 1u);
        if (ticket == GRID_BLOCKS - 1u) {
            // Last block: all partials globally visible (threadfence + atomic order).
            const float ps = atomicAdd(&g_pos_sum, 0.0f);
            const float ts = atomicAdd(&g_tot_sum, 0.0f);
            const float pn = atomicAdd(&g_pos_cnt, 0.0f);

            const float total     = (float)NHW_;
            const float neg_num   = total - pn;
            const float pos_ratio = pn / total;
            const float neg_ratio = 1.0f - pos_ratio;
            const float cf        = (float)C_;
            const float mse_pos   = ps / (pn * cf);
            const float mse_neg   = (ts - ps) / (neg_num * cf);
            out[0] = pos_ratio * mse_neg + neg_ratio * mse_pos;

            // Reset accumulators so the next graph replay starts clean.
            g_pos_sum = 0.0f;
            g_tot_sum = 0.0f;
            g_pos_cnt = 0.0f;
            __threadfence();
            g_done = 0u;
        }
    }
}

extern "C" void kernel_launch(void* const* d_in, const int* in_sizes, int n_in,
                              void* d_out, int out_size)
{
    const float4* x4   = (const float4*)d_in[0];   // x        (16,3,512,512)
    const float4* ae4  = (const float4*)d_in[1];   // out_ae   (16,3,512,512)
    const float4* seg4 = (const float4*)d_in[2];   // out_seg  (16,1,512,512)
    float* out = (float*)d_out;

    wmse_kernel<<<GRID_BLOCKS, BLOCK_THREADS>>>(x4, ae4, seg4, out);
}